// round 4
// baseline (speedup 1.0000x reference)
#include <cuda_runtime.h>

// ---------------------------------------------------------------------------
// CubeAttention, tiled. N=20, D=64, CAP=32, SCOPE=2, WIDTH=5, P=125.
//   Q = SE@Wq+bq ; K = SE@Wk[96:] ; V = SE@Wv[96:]
//   krel/vrel[p] = relpos_flat[p]@W[:96] + b
//   QR[v][p] = Q[v].krel[p]           (precomputed GEMM)
//   logits[v][p] = QR[v][p] + Q[v].K[gather(v,p)]   (reference mask quirk kept)
//   out[v] = (softmax . (V[gather] + vrel)) @ Wo + bo
// Tiling: block = 2x2x2 voxels; gather region = 6x6x6 rows staged in smem.
// ---------------------------------------------------------------------------

#define NV 8000
#define NP 125

__device__ float g_Q[NV * 64];
__device__ float g_K[NV * 64];
__device__ float g_V[NV * 64];
__device__ float g_krelT[64 * NP];   // [k][p]
__device__ float g_vrel[NP * 64];    // [p][c]
__device__ float g_QR[NV * 128];     // [v][p] stride 128

// ---------------------------------------------------------------------------
// Prep: blocked GEMM. Block = 32 rows x 64 ch, one of {Q,K,V} per blockIdx.y.
// ---------------------------------------------------------------------------
__global__ void __launch_bounds__(256) prep_kernel(
    const float* __restrict__ se,
    const float* __restrict__ Wq, const float* __restrict__ bq,
    const float* __restrict__ Wk, const float* __restrict__ Wv)
{
    __shared__ float Wsm[64 * 64];
    __shared__ float ssm[32 * 64];
    int sel = blockIdx.y;
    int tid = threadIdx.x;
    const float* W = (sel == 0) ? Wq : (sel == 1) ? (Wk + 96 * 64) : (Wv + 96 * 64);

    #pragma unroll
    for (int i = tid; i < 4096; i += 256) Wsm[i] = W[i];
    int base = blockIdx.x * 32;
    #pragma unroll
    for (int i = tid; i < 2048; i += 256) ssm[i] = se[base * 64 + i];
    __syncthreads();

    int c  = tid & 63;
    int r0 = (tid >> 6) * 8;
    float acc[8];
    float bias = (sel == 0) ? bq[c] : 0.0f;
    #pragma unroll
    for (int j = 0; j < 8; j++) acc[j] = bias;

    #pragma unroll 4
    for (int k = 0; k < 64; k++) {
        float wv = Wsm[k * 64 + c];
        #pragma unroll
        for (int j = 0; j < 8; j++)
            acc[j] = fmaf(ssm[(r0 + j) * 64 + k], wv, acc[j]);
    }
    float* out = (sel == 0) ? g_Q : (sel == 1) ? g_K : g_V;
    #pragma unroll
    for (int j = 0; j < 8; j++) out[(base + r0 + j) * 64 + c] = acc[j];
}

// ---------------------------------------------------------------------------
// Rel tables. Block = p, thread = channel. p = a*25 + b*5 + c.
// ---------------------------------------------------------------------------
__global__ void __launch_bounds__(64) rel_kernel(
    const float* __restrict__ rw,
    const float* __restrict__ Wk, const float* __restrict__ bk,
    const float* __restrict__ Wv, const float* __restrict__ bv)
{
    int p  = blockIdx.x;
    int ch = threadIdx.x;
    int a = p / 25, b = (p / 5) % 5, c = p % 5;

    float kk = bk[ch];
    float vv = bv[ch];
    #pragma unroll 8
    for (int j = 0; j < 32; j++) {
        float ra = rw[a * 32 + j];
        float rb = rw[b * 32 + j];
        float rc = rw[c * 32 + j];
        kk = fmaf(ra, Wk[j * 64 + ch], kk);
        kk = fmaf(rb, Wk[(32 + j) * 64 + ch], kk);
        kk = fmaf(rc, Wk[(64 + j) * 64 + ch], kk);
        vv = fmaf(ra, Wv[j * 64 + ch], vv);
        vv = fmaf(rb, Wv[(32 + j) * 64 + ch], vv);
        vv = fmaf(rc, Wv[(64 + j) * 64 + ch], vv);
    }
    g_krelT[ch * NP + p] = kk;     // transposed for QR kernel
    g_vrel[p * 64 + ch]  = vv;
}

// ---------------------------------------------------------------------------
// QR[v][p] = Q[v] . krel[p].  Block = 4 voxels x 128 threads.
// ---------------------------------------------------------------------------
__global__ void __launch_bounds__(512) qr_kernel()
{
    __shared__ float qsm[4 * 64];
    int tid = threadIdx.x;
    int h = tid >> 7;            // voxel slot 0..3
    int p = tid & 127;
    int v = blockIdx.x * 4 + h;
    if (p < 64) qsm[h * 64 + p] = g_Q[v * 64 + p];
    __syncthreads();
    if (p < NP) {
        float acc = 0.0f;
        #pragma unroll 8
        for (int k = 0; k < 64; k++)
            acc = fmaf(qsm[h * 64 + k], g_krelT[k * NP + p], acc);
        g_QR[v * 128 + p] = acc;
    }
}

// ---------------------------------------------------------------------------
// Tiled attention. Block = 2x2x2 voxels, 256 threads, ~163KB dynamic smem.
// Smem float offsets:
//   kst  [64][217]   0      (K transposed, 217-pad for conflict-free access)
//   vst  [344][64]   13888  (rows 0..215 data, 216..340 vrel)
//   qt   [64][8]     35904
//   sc   [8][128]    36416  (QR -> logits -> scores)
//   wt   [8][344]    37440  (value-phase weight table)
//   pts  [2][512]    40192
//   ts   [512]       41216
// ---------------------------------------------------------------------------
#define SMEM_FLOATS 41728

__global__ void __launch_bounds__(256) attn_kernel(
    const float* __restrict__ Wo, const float* __restrict__ bo,
    float* __restrict__ out)
{
    extern __shared__ float sm[];
    float* kst = sm;
    float* vst = sm + 13888;
    float* qt  = sm + 35904;
    float* sc  = sm + 36416;
    float* wt  = sm + 37440;
    float* pts = sm + 40192;
    float* ts  = sm + 41216;

    int tid = threadIdx.x;
    int bz = blockIdx.x % 10, by = (blockIdx.x / 10) % 10, bx = blockIdx.x / 100;
    int X = bx * 2, Y = by * 2, Z = bz * 2;

    // ---- stage region K (transposed) + V, vrel rows, q, QR ----
    for (int i = tid; i < 216 * 64; i += 256) {
        int r = i >> 6, c = i & 63;
        int rx = r / 36, rem = r - rx * 36, ry = rem / 6, rz = rem - ry * 6;
        int dx = X - 2 + rx, dy = Y - 2 + ry, dz = Z - 2 + rz;
        bool ok = ((unsigned)dx < 20u) & ((unsigned)dy < 20u) & ((unsigned)dz < 20u);
        int g = ((dx * 20 + dy) * 20 + dz) * 64 + c;
        kst[c * 217 + r] = ok ? g_K[g] : 0.0f;
        vst[i]           = ok ? g_V[g] : 0.0f;
    }
    for (int i = tid; i < NP * 64; i += 256)
        vst[216 * 64 + i] = g_vrel[i];
    for (int i = tid; i < 512; i += 256) {
        int v = i >> 6, k = i & 63;
        int gv = ((X + (v >> 2)) * 20 + Y + ((v >> 1) & 1)) * 20 + Z + (v & 1);
        qt[k * 8 + v] = g_Q[gv * 64 + k];
    }
    for (int i = tid; i < 1024; i += 256) {
        int v = i >> 7, p = i & 127;
        int gv = ((X + (v >> 2)) * 20 + Y + ((v >> 1) & 1)) * 20 + Z + (v & 1);
        sc[i] = (p < NP) ? g_QR[gv * 128 + p] : -1e30f;
    }
    __syncthreads();

    // ---- phase 1: rowdot GEMM [8 x 216] + scatter to logits ----
    if (tid < 216) {
        int r = tid;
        float acc[8];
        #pragma unroll
        for (int j = 0; j < 8; j++) acc[j] = 0.0f;
        #pragma unroll 4
        for (int k = 0; k < 64; k++) {
            float kv = kst[k * 217 + r];
            float4 qa = *(const float4*)(qt + k * 8);
            float4 qb = *(const float4*)(qt + k * 8 + 4);
            acc[0] = fmaf(kv, qa.x, acc[0]); acc[1] = fmaf(kv, qa.y, acc[1]);
            acc[2] = fmaf(kv, qa.z, acc[2]); acc[3] = fmaf(kv, qa.w, acc[3]);
            acc[4] = fmaf(kv, qb.x, acc[4]); acc[5] = fmaf(kv, qb.y, acc[5]);
            acc[6] = fmaf(kv, qb.z, acc[6]); acc[7] = fmaf(kv, qb.w, acc[7]);
        }
        int rx = r / 36, rem = r - rx * 36, ry = rem / 6, rz = rem - ry * 6;
        #pragma unroll
        for (int v = 0; v < 8; v++) {
            int lx = v >> 2, ly = (v >> 1) & 1, lz = v & 1;
            int a = ry - ly, b = rx - lx, c = rz - lz;
            if (((unsigned)a < 5u) & ((unsigned)b < 5u) & ((unsigned)c < 5u)) {
                int p = (a * 5 + b) * 5 + c;
                // mask quirk: validity at (x+a, y+b, z+c), strict [1,19]
                int mx = X + lx + a - 2, my = Y + ly + b - 2, mz = Z + lz + c - 2;
                bool mv = (mx >= 1) & (mx <= 19) & (my >= 1) & (my <= 19)
                        & (mz >= 1) & (mz <= 19);
                sc[v * 128 + p] = mv ? (sc[v * 128 + p] + acc[v]) : -1e9f;
            }
        }
    }
    __syncthreads();

    // ---- phase 2: per-voxel softmax (warp = voxel) ----
    {
        int w = tid >> 5, lane = tid & 31;
        float l0 = sc[w * 128 + lane];
        float l1 = sc[w * 128 + lane + 32];
        float l2 = sc[w * 128 + lane + 64];
        float l3 = (lane < 29) ? sc[w * 128 + lane + 96] : -1e30f;
        float m = fmaxf(fmaxf(l0, l1), fmaxf(l2, l3));
        #pragma unroll
        for (int o = 16; o; o >>= 1)
            m = fmaxf(m, __shfl_xor_sync(0xffffffffu, m, o));
        float e0 = __expf(l0 - m), e1 = __expf(l1 - m);
        float e2 = __expf(l2 - m), e3 = __expf(l3 - m);
        float s = (e0 + e1) + (e2 + e3);
        #pragma unroll
        for (int o = 16; o; o >>= 1)
            s += __shfl_xor_sync(0xffffffffu, s, o);
        float inv = 1.0f / s;
        sc[w * 128 + lane]      = e0 * inv;
        sc[w * 128 + lane + 32] = e1 * inv;
        sc[w * 128 + lane + 64] = e2 * inv;
        if (lane < 29) sc[w * 128 + lane + 96] = e3 * inv;
    }
    __syncthreads();

    // ---- weight table for value GEMM (masked scores are exact zeros) ----
    #pragma unroll
    for (int v = 0; v < 8; v++) {
        int lx = v >> 2, ly = (v >> 1) & 1, lz = v & 1;
        for (int r = tid; r < 341; r += 256) {
            float w;
            if (r < 216) {
                int rx = r / 36, rem = r - rx * 36, ry = rem / 6, rz = rem - ry * 6;
                int a = ry - ly, b = rx - lx, c = rz - lz;
                w = (((unsigned)a < 5u) & ((unsigned)b < 5u) & ((unsigned)c < 5u))
                    ? sc[v * 128 + (a * 5 + b) * 5 + c] : 0.0f;
            } else {
                w = sc[v * 128 + (r - 216)];
            }
            wt[v * 344 + r] = w;
        }
    }
    __syncthreads();

    // ---- phase 3: value GEMM [8 x 341] @ [341 x 64] ----
    {
        int w = tid >> 5, lane = tid & 31;
        int rh = w >> 2, vg = (w >> 1) & 1, ch = w & 1;
        int cm = ch * 32 + lane;
        int v0 = vg * 4;
        int rA = rh ? 171 : 0;
        int rB = rh ? 341 : 171;
        float a0 = 0, a1 = 0, a2 = 0, a3 = 0;
        const float* w0 = wt + (v0 + 0) * 344;
        const float* w1 = wt + (v0 + 1) * 344;
        const float* w2 = wt + (v0 + 2) * 344;
        const float* w3 = wt + (v0 + 3) * 344;
        #pragma unroll 2
        for (int r = rA; r < rB; r++) {
            float val = vst[r * 64 + cm];
            a0 = fmaf(w0[r], val, a0);
            a1 = fmaf(w1[r], val, a1);
            a2 = fmaf(w2[r], val, a2);
            a3 = fmaf(w3[r], val, a3);
        }
        pts[rh * 512 + (v0 + 0) * 64 + cm] = a0;
        pts[rh * 512 + (v0 + 1) * 64 + cm] = a1;
        pts[rh * 512 + (v0 + 2) * 64 + cm] = a2;
        pts[rh * 512 + (v0 + 3) * 64 + cm] = a3;
    }
    __syncthreads();
    for (int i = tid; i < 512; i += 256)
        ts[i] = pts[i] + pts[512 + i];
    __syncthreads();

    // ---- epilogue: @Wo + bo ----
    {
        int c = tid & 63, vg = tid >> 6;
        #pragma unroll
        for (int vv = 0; vv < 2; vv++) {
            int v = vg * 2 + vv;
            float o = bo[c];
            #pragma unroll 8
            for (int k = 0; k < 64; k++)
                o = fmaf(ts[v * 64 + k], Wo[k * 64 + c], o);
            int gv = ((X + (v >> 2)) * 20 + Y + ((v >> 1) & 1)) * 20 + Z + (v & 1);
            out[gv * 64 + c] = o;
        }
    }
}

// ---------------------------------------------------------------------------
// Launch
// d_in: 0=spatial_embeddings 1=relpos_w 2=Wq 3=bq 4=Wk 5=bk 6=Wv 7=bv 8=Wo 9=bo
// ---------------------------------------------------------------------------
extern "C" void kernel_launch(void* const* d_in, const int* in_sizes, int n_in,
                              void* d_out, int out_size)
{
    const float* se = (const float*)d_in[0];
    const float* rw = (const float*)d_in[1];
    const float* Wq = (const float*)d_in[2];
    const float* bq = (const float*)d_in[3];
    const float* Wk = (const float*)d_in[4];
    const float* bk = (const float*)d_in[5];
    const float* Wv = (const float*)d_in[6];
    const float* bv = (const float*)d_in[7];
    const float* Wo = (const float*)d_in[8];
    const float* bo = (const float*)d_in[9];
    float* out = (float*)d_out;

    cudaFuncSetAttribute(attn_kernel, cudaFuncAttributeMaxDynamicSharedMemorySize,
                         SMEM_FLOATS * 4);

    prep_kernel<<<dim3(250, 3), 256>>>(se, Wq, bq, Wk, Wv);
    rel_kernel<<<NP, 64>>>(rw, Wk, bk, Wv, bv);
    qr_kernel<<<2000, 512>>>();
    attn_kernel<<<1000, 256, SMEM_FLOATS * 4>>>(Wo, bo, out);
}

// round 5
// speedup vs baseline: 1.5453x; 1.5453x over previous
#include <cuda_runtime.h>

// ---------------------------------------------------------------------------
// CubeAttention, tiled v2. N=20, D=64, CAP=32, SCOPE=2, WIDTH=5, P=125.
//   Q = SE@Wq+bq ; K = SE@Wk[96:] ; V = SE@Wv[96:]  (K,V stored ZERO-PADDED 22^3)
//   krel/vrel[p] = relpos_flat[p]@W[:96] + b ;  QR[v][p] = Q[v].krel[p]
//   logits[v][p] = QR[v][p] + Q[v].K[gather(v,p)]   (zero rows => QR only)
//   mask quirk: validity at (x+a,y+b,z+c) strict [1,19]; gather at (x+b,y+a,z+c)
// Block = 2x2x2 voxels, 256 thr, 61KB smem (3 CTAs/SM). K staged, then V
// staged into the SAME buffer after softmax.
// ---------------------------------------------------------------------------

#define NV 8000
#define NP 125
#define PD 22
#define PR (PD * PD * PD)
#define RS 65                       // padded region row stride (conflict-free)
#define SM_KST 0                    // [216][65] = 14040
#define SM_SC  14040                // [8][128]  = 1024
#define SM_QT  15064                // [64][8] (phase1) / ts[8][64] (epilogue)
#define SMF    15576                // floats

__device__ float g_Q[NV * 64];
__device__ float g_K[PR * 64];      // zero-padded (statics are zero-init)
__device__ float g_V[PR * 64];
__device__ float g_krelT[64 * NP];
__device__ float g_vrel[NP * 64];
__device__ float g_QR[NV * 128];

// ---------------------------------------------------------------------------
// Prep: blocked GEMM, 32 rows/block. Q unpadded; K/V into padded cube.
// ---------------------------------------------------------------------------
__global__ void __launch_bounds__(256) prep_kernel(
    const float* __restrict__ se,
    const float* __restrict__ Wq, const float* __restrict__ bq,
    const float* __restrict__ Wk, const float* __restrict__ Wv)
{
    __shared__ float Wsm[64 * 64];
    __shared__ float ssm[32 * 64];
    int sel = blockIdx.y;
    int tid = threadIdx.x;
    const float* W = (sel == 0) ? Wq : (sel == 1) ? (Wk + 96 * 64) : (Wv + 96 * 64);

    #pragma unroll
    for (int i = tid; i < 4096; i += 256) Wsm[i] = W[i];
    int base = blockIdx.x * 32;
    #pragma unroll
    for (int i = tid; i < 2048; i += 256) ssm[i] = se[base * 64 + i];
    __syncthreads();

    int c  = tid & 63;
    int r0 = (tid >> 6) * 8;
    float acc[8];
    float bias = (sel == 0) ? bq[c] : 0.0f;
    #pragma unroll
    for (int j = 0; j < 8; j++) acc[j] = bias;

    #pragma unroll 4
    for (int k = 0; k < 64; k++) {
        float wv = Wsm[k * 64 + c];
        #pragma unroll
        for (int j = 0; j < 8; j++)
            acc[j] = fmaf(ssm[(r0 + j) * 64 + k], wv, acc[j]);
    }
    #pragma unroll
    for (int j = 0; j < 8; j++) {
        int v = base + r0 + j;
        if (sel == 0) {
            g_Q[v * 64 + c] = acc[j];
        } else {
            int x = v / 400, y = (v / 20) % 20, z = v % 20;
            int pi = ((x + 2) * PD + (y + 2)) * PD + (z + 2);
            ((sel == 1) ? g_K : g_V)[pi * 64 + c] = acc[j];
        }
    }
}

// ---------------------------------------------------------------------------
// Rel tables. Block = p, thread = channel. p = a*25 + b*5 + c.
// ---------------------------------------------------------------------------
__global__ void __launch_bounds__(64) rel_kernel(
    const float* __restrict__ rw,
    const float* __restrict__ Wk, const float* __restrict__ bk,
    const float* __restrict__ Wv, const float* __restrict__ bv)
{
    int p  = blockIdx.x;
    int ch = threadIdx.x;
    int a = p / 25, b = (p / 5) % 5, c = p % 5;

    float kk = bk[ch];
    float vv = bv[ch];
    #pragma unroll 8
    for (int j = 0; j < 32; j++) {
        float ra = rw[a * 32 + j];
        float rb = rw[b * 32 + j];
        float rc = rw[c * 32 + j];
        kk = fmaf(ra, Wk[j * 64 + ch], kk);
        kk = fmaf(rb, Wk[(32 + j) * 64 + ch], kk);
        kk = fmaf(rc, Wk[(64 + j) * 64 + ch], kk);
        vv = fmaf(ra, Wv[j * 64 + ch], vv);
        vv = fmaf(rb, Wv[(32 + j) * 64 + ch], vv);
        vv = fmaf(rc, Wv[(64 + j) * 64 + ch], vv);
    }
    g_krelT[ch * NP + p] = kk;
    g_vrel[p * 64 + ch]  = vv;
}

// ---------------------------------------------------------------------------
// QR[v][p] = Q[v] . krel[p].  Block = 4 voxels x 128 threads.
// ---------------------------------------------------------------------------
__global__ void __launch_bounds__(512) qr_kernel()
{
    __shared__ float qsm[4 * 64];
    int tid = threadIdx.x;
    int h = tid >> 7;
    int p = tid & 127;
    int v = blockIdx.x * 4 + h;
    if (p < 64) qsm[h * 64 + p] = g_Q[v * 64 + p];
    __syncthreads();
    if (p < NP) {
        float acc = 0.0f;
        #pragma unroll 8
        for (int k = 0; k < 64; k++)
            acc = fmaf(qsm[h * 64 + k], g_krelT[k * NP + p], acc);
        g_QR[v * 128 + p] = acc;
    }
}

// ---------------------------------------------------------------------------
// Tiled attention v2. Block = 2x2x2 voxels, 256 threads, 61KB smem.
// ---------------------------------------------------------------------------
__global__ void __launch_bounds__(256) attn_kernel(
    const float* __restrict__ Wo, const float* __restrict__ bo,
    float* __restrict__ out)
{
    extern __shared__ float sm[];
    float* kst = sm + SM_KST;
    float* sc  = sm + SM_SC;
    float* qt  = sm + SM_QT;   // q (phase1), then ts (value/epilogue)

    int tid = threadIdx.x;
    int bz = blockIdx.x % 10, by = (blockIdx.x / 10) % 10, bx = blockIdx.x / 100;
    int X = bx * 2, Y = by * 2, Z = bz * 2;
    int pbase = ((X * PD + Y) * PD + Z) * 64;   // padded coord of region origin
                                                // (X-2+rx)+2 = X+rx

    // ---- stage K region, q, QR ----
    #pragma unroll 4
    for (int i = tid; i < 216 * 64; i += 256) {
        int r = i >> 6, c = i & 63;
        int rx = r / 36, rem = r - rx * 36, ry = rem / 6, rz = rem - ry * 6;
        kst[r * RS + c] = g_K[pbase + ((rx * PD + ry) * PD + rz) * 64 + c];
    }
    #pragma unroll
    for (int i = tid; i < 512; i += 256) {
        int v = i >> 6, k = i & 63;
        int gv = ((X + (v >> 2)) * 20 + Y + ((v >> 1) & 1)) * 20 + Z + (v & 1);
        qt[k * 8 + v] = g_Q[gv * 64 + k];
    }
    #pragma unroll
    for (int i = tid; i < 1024; i += 256) {
        int v = i >> 7, p = i & 127;
        int gv = ((X + (v >> 2)) * 20 + Y + ((v >> 1) & 1)) * 20 + Z + (v & 1);
        sc[i] = (p < NP) ? g_QR[gv * 128 + p] : -1e30f;
    }
    __syncthreads();

    // ---- phase 1: rowdot [8 x 216] + masked scatter into logits ----
    if (tid < 216) {
        int r = tid;
        float acc[8];
        #pragma unroll
        for (int j = 0; j < 8; j++) acc[j] = 0.0f;
        #pragma unroll 4
        for (int k = 0; k < 64; k++) {
            float kv = kst[r * RS + k];
            float4 qa = *(const float4*)(qt + k * 8);
            float4 qb = *(const float4*)(qt + k * 8 + 4);
            acc[0] = fmaf(kv, qa.x, acc[0]); acc[1] = fmaf(kv, qa.y, acc[1]);
            acc[2] = fmaf(kv, qa.z, acc[2]); acc[3] = fmaf(kv, qa.w, acc[3]);
            acc[4] = fmaf(kv, qb.x, acc[4]); acc[5] = fmaf(kv, qb.y, acc[5]);
            acc[6] = fmaf(kv, qb.z, acc[6]); acc[7] = fmaf(kv, qb.w, acc[7]);
        }
        int rx = r / 36, rem = r - rx * 36, ry = rem / 6, rz = rem - ry * 6;
        #pragma unroll
        for (int v = 0; v < 8; v++) {
            int lx = v >> 2, ly = (v >> 1) & 1, lz = v & 1;
            int a = ry - ly, b = rx - lx, c = rz - lz;
            if (((unsigned)a < 5u) & ((unsigned)b < 5u) & ((unsigned)c < 5u)) {
                int p = (a * 5 + b) * 5 + c;
                int mx = X + lx + a - 2, my = Y + ly + b - 2, mz = Z + lz + c - 2;
                bool mv = (mx >= 1) & (mx <= 19) & (my >= 1) & (my <= 19)
                        & (mz >= 1) & (mz <= 19);
                sc[v * 128 + p] = mv ? (sc[v * 128 + p] + acc[v]) : -1e9f;
            }
        }
    }
    __syncthreads();

    // ---- phase 2: per-voxel softmax (warp = voxel) ----
    {
        int w = tid >> 5, lane = tid & 31;
        float l0 = sc[w * 128 + lane];
        float l1 = sc[w * 128 + lane + 32];
        float l2 = sc[w * 128 + lane + 64];
        float l3 = (lane < 29) ? sc[w * 128 + lane + 96] : -1e30f;
        float m = fmaxf(fmaxf(l0, l1), fmaxf(l2, l3));
        #pragma unroll
        for (int o = 16; o; o >>= 1)
            m = fmaxf(m, __shfl_xor_sync(0xffffffffu, m, o));
        float e0 = __expf(l0 - m), e1 = __expf(l1 - m);
        float e2 = __expf(l2 - m), e3 = __expf(l3 - m);
        float s = (e0 + e1) + (e2 + e3);
        #pragma unroll
        for (int o = 16; o; o >>= 1)
            s += __shfl_xor_sync(0xffffffffu, s, o);
        float inv = 1.0f / s;
        sc[w * 128 + lane]      = e0 * inv;
        sc[w * 128 + lane + 32] = e1 * inv;
        sc[w * 128 + lane + 64] = e2 * inv;
        if (lane < 29) sc[w * 128 + lane + 96] = e3 * inv;
    }
    __syncthreads();

    // ---- stage V region over the K buffer ----
    #pragma unroll 4
    for (int i = tid; i < 216 * 64; i += 256) {
        int r = i >> 6, c = i & 63;
        int rx = r / 36, rem = r - rx * 36, ry = rem / 6, rz = rem - ry * 6;
        kst[r * RS + c] = g_V[pbase + ((rx * PD + ry) * PD + rz) * 64 + c];
    }
    __syncthreads();

    // ---- phase 3: value accumulation (warp = voxel) ----
    {
        int w = tid >> 5, lane = tid & 31;
        int lx = w >> 2, ly = (w >> 1) & 1, lz = w & 1;
        float a0 = 0.0f, a1 = 0.0f;
        #pragma unroll 5
        for (int p = 0; p < NP; p++) {
            float s = sc[w * 128 + p];
            if (s != 0.0f) {            // uniform across warp
                int pa = p / 25, pb = (p / 5) % 5, pc = p % 5;
                int r = (lx + pb) * 36 + (ly + pa) * 6 + (lz + pc);
                a0 = fmaf(s, kst[r * RS + lane]      + g_vrel[p * 64 + lane],      a0);
                a1 = fmaf(s, kst[r * RS + lane + 32] + g_vrel[p * 64 + lane + 32], a1);
            }
        }
        qt[w * 64 + lane]      = a0;    // qt reused as ts[8][64]
        qt[w * 64 + lane + 32] = a1;
    }
    __syncthreads();

    // ---- epilogue: @Wo + bo (all 256 threads, 2 outputs each) ----
    #pragma unroll
    for (int id = tid; id < 512; id += 256) {
        int v = id >> 6, c = id & 63;
        float o = bo[c];
        #pragma unroll 8
        for (int k = 0; k < 64; k++)
            o = fmaf(qt[v * 64 + k], Wo[k * 64 + c], o);
        int gv = ((X + (v >> 2)) * 20 + Y + ((v >> 1) & 1)) * 20 + Z + (v & 1);
        out[gv * 64 + c] = o;
    }
}

// ---------------------------------------------------------------------------
// Launch
// d_in: 0=spatial_embeddings 1=relpos_w 2=Wq 3=bq 4=Wk 5=bk 6=Wv 7=bv 8=Wo 9=bo
// ---------------------------------------------------------------------------
extern "C" void kernel_launch(void* const* d_in, const int* in_sizes, int n_in,
                              void* d_out, int out_size)
{
    const float* se = (const float*)d_in[0];
    const float* rw = (const float*)d_in[1];
    const float* Wq = (const float*)d_in[2];
    const float* bq = (const float*)d_in[3];
    const float* Wk = (const float*)d_in[4];
    const float* bk = (const float*)d_in[5];
    const float* Wv = (const float*)d_in[6];
    const float* bv = (const float*)d_in[7];
    const float* Wo = (const float*)d_in[8];
    const float* bo = (const float*)d_in[9];
    float* out = (float*)d_out;

    cudaFuncSetAttribute(attn_kernel, cudaFuncAttributeMaxDynamicSharedMemorySize,
                         SMF * 4);

    prep_kernel<<<dim3(250, 3), 256>>>(se, Wq, bq, Wk, Wv);
    rel_kernel<<<NP, 64>>>(rw, Wk, bk, Wv, bv);
    qr_kernel<<<2000, 512>>>();
    attn_kernel<<<1000, 256, SMF * 4>>>(Wo, bo, out);
}

// round 6
// speedup vs baseline: 1.9314x; 1.2498x over previous
#include <cuda_runtime.h>

// ---------------------------------------------------------------------------
// CubeAttention v3. N=20, D=64, CAP=32, SCOPE=2, WIDTH=5, P=125.
//   Q  = SE@Wq+bq ; K = SE@Wk[96:]      (zero-padded 22^3 cube)
//   W2 = Wv[96:]@Wo ; V' = SE@W2        (value rows pre-multiplied by Wo)
//   krel[p] = relpos@Wk[:96]+bk ; vrel'[p] = (relpos@Wv[:96]+bv)@Wo
//   QR[v][p] = Q[v].krel[p]
//   logits[v][p] = QR + Q[v].K[gather]  (zero pad rows => QR only)
//   out[v] = sum_p sc[p]*(V'[gather] + vrel'[p]) + bo     <-- no epilogue
// mask quirk: validity at (x+a,y+b,z+c) strict [1,19]; gather at (x+b,y+a,z+c)
// Block = 2x2x2 voxels, 256 thr, 73KB smem (3 CTAs/SM).
// ---------------------------------------------------------------------------

#define NV 8000
#define NP 125
#define PD 22
#define PR (PD * PD * PD)
#define RS 65
#define SM_VST 0                    // [216][65] = 14040  (K, then V')
#define SM_SC  14040                // [8][128]
#define SM_QT  15064                // [64][8]
#define SM_WT  15576                // [341][8] = 2728
#define SMF    18304

__device__ float g_Q[NV * 64];
__device__ float g_K[PR * 64];      // zero-padded
__device__ float g_V[PR * 64];      // V' (pre-Wo), zero-padded
__device__ float g_W2[64 * 64];
__device__ float g_krelT[64 * NP];
__device__ float g_vrel[NP * 64];
__device__ float g_vrel2[NP * 64];  // vrel @ Wo
__device__ float g_QR[NV * 128];

// ---------------------------------------------------------------------------
// K1: rel tables (blocks 0..124) + W2 = Wv[96:]@Wo (blocks 125..188)
// ---------------------------------------------------------------------------
__global__ void __launch_bounds__(64) rel_w2_kernel(
    const float* __restrict__ rw,
    const float* __restrict__ Wk, const float* __restrict__ bk,
    const float* __restrict__ Wv, const float* __restrict__ bv,
    const float* __restrict__ Wo)
{
    int blk = blockIdx.x;
    int ch  = threadIdx.x;
    if (blk >= NP) {                       // W2 row
        int i = blk - NP;
        float acc = 0.0f;
        #pragma unroll 8
        for (int k = 0; k < 64; k++)
            acc = fmaf(Wv[(96 + i) * 64 + k], Wo[k * 64 + ch], acc);
        g_W2[i * 64 + ch] = acc;
        return;
    }
    int p = blk;
    int a = p / 25, b = (p / 5) % 5, c = p % 5;
    float kk = bk[ch];
    float vv = bv[ch];
    #pragma unroll 8
    for (int j = 0; j < 32; j++) {
        float ra = rw[a * 32 + j];
        float rb = rw[b * 32 + j];
        float rc = rw[c * 32 + j];
        kk = fmaf(ra, Wk[j * 64 + ch], kk);
        kk = fmaf(rb, Wk[(32 + j) * 64 + ch], kk);
        kk = fmaf(rc, Wk[(64 + j) * 64 + ch], kk);
        vv = fmaf(ra, Wv[j * 64 + ch], vv);
        vv = fmaf(rb, Wv[(32 + j) * 64 + ch], vv);
        vv = fmaf(rc, Wv[(64 + j) * 64 + ch], vv);
    }
    g_krelT[ch * NP + p] = kk;
    g_vrel[p * 64 + ch]  = vv;
}

// ---------------------------------------------------------------------------
// K2: prep. sel 0: Q = SE@Wq+bq ; 1: K = SE@Wk[96:] ; 2: V' = SE@W2.
// ---------------------------------------------------------------------------
__global__ void __launch_bounds__(256) prep_kernel(
    const float* __restrict__ se,
    const float* __restrict__ Wq, const float* __restrict__ bq,
    const float* __restrict__ Wk)
{
    __shared__ float Wsm[64 * 64];
    __shared__ float ssm[32 * 64];
    int sel = blockIdx.y;
    int tid = threadIdx.x;
    const float* W = (sel == 0) ? Wq : (sel == 1) ? (Wk + 96 * 64) : g_W2;

    #pragma unroll
    for (int i = tid; i < 4096; i += 256) Wsm[i] = W[i];
    int base = blockIdx.x * 32;
    #pragma unroll
    for (int i = tid; i < 2048; i += 256) ssm[i] = se[base * 64 + i];
    __syncthreads();

    int c  = tid & 63;
    int r0 = (tid >> 6) * 8;
    float acc[8];
    float bias = (sel == 0) ? bq[c] : 0.0f;
    #pragma unroll
    for (int j = 0; j < 8; j++) acc[j] = bias;

    #pragma unroll 4
    for (int k = 0; k < 64; k++) {
        float wv = Wsm[k * 64 + c];
        #pragma unroll
        for (int j = 0; j < 8; j++)
            acc[j] = fmaf(ssm[(r0 + j) * 64 + k], wv, acc[j]);
    }
    #pragma unroll
    for (int j = 0; j < 8; j++) {
        int v = base + r0 + j;
        if (sel == 0) {
            g_Q[v * 64 + c] = acc[j];
        } else {
            int x = v / 400, y = (v / 20) % 20, z = v % 20;
            int pi = ((x + 2) * PD + (y + 2)) * PD + (z + 2);
            ((sel == 1) ? g_K : g_V)[pi * 64 + c] = acc[j];
        }
    }
}

// ---------------------------------------------------------------------------
// K3: QR (blocks 0..1999, 4 voxels each) + vrel2 = vrel@Wo (blocks 2000..2124)
// ---------------------------------------------------------------------------
__global__ void __launch_bounds__(512) qr_kernel(const float* __restrict__ Wo)
{
    __shared__ float qsm[4 * 64];
    int tid = threadIdx.x;
    if (blockIdx.x >= 2000) {
        int p = blockIdx.x - 2000;
        if (tid < 64) {
            float acc = 0.0f;
            #pragma unroll 8
            for (int k = 0; k < 64; k++)
                acc = fmaf(g_vrel[p * 64 + k], Wo[k * 64 + tid], acc);
            g_vrel2[p * 64 + tid] = acc;
        }
        return;
    }
    int h = tid >> 7;
    int p = tid & 127;
    int v = blockIdx.x * 4 + h;
    if (p < 64) qsm[h * 64 + p] = g_Q[v * 64 + p];
    __syncthreads();
    if (p < NP) {
        float acc = 0.0f;
        #pragma unroll 8
        for (int k = 0; k < 64; k++)
            acc = fmaf(qsm[h * 64 + k], g_krelT[k * NP + p], acc);
        g_QR[v * 128 + p] = acc;
    }
}

// ---------------------------------------------------------------------------
// K4: attention. 2x2x2 voxels / block, 256 threads.
// ---------------------------------------------------------------------------
__global__ void __launch_bounds__(256) attn_kernel(
    const float* __restrict__ bo, float* __restrict__ out)
{
    extern __shared__ float sm[];
    float* vst = sm + SM_VST;
    float* sc  = sm + SM_SC;
    float* qt  = sm + SM_QT;
    float* wt  = sm + SM_WT;

    int tid = threadIdx.x;
    int bz = blockIdx.x % 10, by = (blockIdx.x / 10) % 10, bx = blockIdx.x / 100;
    int X = bx * 2, Y = by * 2, Z = bz * 2;
    int prow = (X * PD + Y) * PD + Z;          // padded row of region origin

    // ---- stage K region (float4 loads), q, QR ----
    const float4* K4 = (const float4*)g_K;
    for (int i = tid; i < 216 * 16; i += 256) {
        int r = i >> 4, c4 = i & 15;
        int rx = r / 36, rem = r - rx * 36, ry = rem / 6, rz = rem - ry * 6;
        float4 f = K4[(prow + (rx * PD + ry) * PD + rz) * 16 + c4];
        float* d = vst + r * RS + c4 * 4;
        d[0] = f.x; d[1] = f.y; d[2] = f.z; d[3] = f.w;
    }
    #pragma unroll
    for (int i = tid; i < 512; i += 256) {
        int v = i >> 6, k = i & 63;
        int gv = ((X + (v >> 2)) * 20 + Y + ((v >> 1) & 1)) * 20 + Z + (v & 1);
        qt[k * 8 + v] = g_Q[gv * 64 + k];
    }
    #pragma unroll
    for (int i = tid; i < 1024; i += 256) {
        int v = i >> 7, p = i & 127;
        int gv = ((X + (v >> 2)) * 20 + Y + ((v >> 1) & 1)) * 20 + Z + (v & 1);
        sc[i] = (p < NP) ? g_QR[gv * 128 + p] : -1e30f;
    }
    __syncthreads();

    // ---- phase 1: rowdot [8 x 216] + masked scatter into logits ----
    if (tid < 216) {
        int r = tid;
        float acc[8];
        #pragma unroll
        for (int j = 0; j < 8; j++) acc[j] = 0.0f;
        #pragma unroll 4
        for (int k = 0; k < 64; k++) {
            float kv = vst[r * RS + k];
            float4 qa = *(const float4*)(qt + k * 8);
            float4 qb = *(const float4*)(qt + k * 8 + 4);
            acc[0] = fmaf(kv, qa.x, acc[0]); acc[1] = fmaf(kv, qa.y, acc[1]);
            acc[2] = fmaf(kv, qa.z, acc[2]); acc[3] = fmaf(kv, qa.w, acc[3]);
            acc[4] = fmaf(kv, qb.x, acc[4]); acc[5] = fmaf(kv, qb.y, acc[5]);
            acc[6] = fmaf(kv, qb.z, acc[6]); acc[7] = fmaf(kv, qb.w, acc[7]);
        }
        int rx = r / 36, rem = r - rx * 36, ry = rem / 6, rz = rem - ry * 6;
        #pragma unroll
        for (int v = 0; v < 8; v++) {
            int lx = v >> 2, ly = (v >> 1) & 1, lz = v & 1;
            int a = ry - ly, b = rx - lx, c = rz - lz;
            if (((unsigned)a < 5u) & ((unsigned)b < 5u) & ((unsigned)c < 5u)) {
                int p = (a * 5 + b) * 5 + c;
                int mx = X + lx + a - 2, my = Y + ly + b - 2, mz = Z + lz + c - 2;
                bool mv = (mx >= 1) & (mx <= 19) & (my >= 1) & (my <= 19)
                        & (mz >= 1) & (mz <= 19);
                sc[v * 128 + p] = mv ? (sc[v * 128 + p] + acc[v]) : -1e9f;
            }
        }
    }
    __syncthreads();

    // ---- phase 2: per-voxel softmax (warp = voxel); masked -> exact 0 ----
    {
        int w = tid >> 5, lane = tid & 31;
        float l0 = sc[w * 128 + lane];
        float l1 = sc[w * 128 + lane + 32];
        float l2 = sc[w * 128 + lane + 64];
        float l3 = (lane < 29) ? sc[w * 128 + lane + 96] : -1e30f;
        float m = fmaxf(fmaxf(l0, l1), fmaxf(l2, l3));
        #pragma unroll
        for (int o = 16; o; o >>= 1)
            m = fmaxf(m, __shfl_xor_sync(0xffffffffu, m, o));
        float e0 = __expf(l0 - m), e1 = __expf(l1 - m);
        float e2 = __expf(l2 - m), e3 = __expf(l3 - m);
        float s = (e0 + e1) + (e2 + e3);
        #pragma unroll
        for (int o = 16; o; o >>= 1)
            s += __shfl_xor_sync(0xffffffffu, s, o);
        float inv = 1.0f / s;
        sc[w * 128 + lane]      = e0 * inv;
        sc[w * 128 + lane + 32] = e1 * inv;
        sc[w * 128 + lane + 64] = e2 * inv;
        if (lane < 29) sc[w * 128 + lane + 96] = e3 * inv;
    }

    // ---- stage V' region over the K buffer (independent of softmax) ----
    {
        const float4* V4 = (const float4*)g_V;
        for (int i = tid; i < 216 * 16; i += 256) {
            int r = i >> 4, c4 = i & 15;
            int rx = r / 36, rem = r - rx * 36, ry = rem / 6, rz = rem - ry * 6;
            float4 f = V4[(prow + (rx * PD + ry) * PD + rz) * 16 + c4];
            float* d = vst + r * RS + c4 * 4;
            d[0] = f.x; d[1] = f.y; d[2] = f.z; d[3] = f.w;
        }
    }
    __syncthreads();

    // ---- build weight table wt[341][8] (zeros for out-of-window) ----
    for (int i = tid; i < 341 * 8; i += 256) {
        int r = i >> 3, v = i & 7;
        float w;
        if (r < 216) {
            int rx = r / 36, rem = r - rx * 36, ry = rem / 6, rz = rem - ry * 6;
            int lx = v >> 2, ly = (v >> 1) & 1, lz = v & 1;
            int a = ry - ly, b = rx - lx, c = rz - lz;
            w = (((unsigned)a < 5u) & ((unsigned)b < 5u) & ((unsigned)c < 5u))
                ? sc[v * 128 + (a * 5 + b) * 5 + c] : 0.0f;
        } else {
            w = sc[v * 128 + (r - 216)];
        }
        wt[i] = w;
    }
    __syncthreads();

    // ---- phase 3: value GEMM  out[8][64] = wt[341][8]^T @ rows[341][64] ----
    // rows 0..215 = V' region (smem), rows 216..340 = vrel2 (global, L1-hot)
    int g = tid >> 6, c = tid & 63;
    float acc[8];
    #pragma unroll
    for (int j = 0; j < 8; j++) acc[j] = 0.0f;
    {
        int rA = (g * 341) >> 2;
        int rB = ((g + 1) * 341) >> 2;
        #pragma unroll 4
        for (int r = rA; r < rB; r++) {
            float val = (r < 216) ? vst[r * RS + c]
                                  : g_vrel2[(r - 216) * 64 + c];
            float4 w0 = *(const float4*)(wt + r * 8);
            float4 w1 = *(const float4*)(wt + r * 8 + 4);
            acc[0] = fmaf(w0.x, val, acc[0]); acc[1] = fmaf(w0.y, val, acc[1]);
            acc[2] = fmaf(w0.z, val, acc[2]); acc[3] = fmaf(w0.w, val, acc[3]);
            acc[4] = fmaf(w1.x, val, acc[4]); acc[5] = fmaf(w1.y, val, acc[5]);
            acc[6] = fmaf(w1.z, val, acc[6]); acc[7] = fmaf(w1.w, val, acc[7]);
        }
    }
    __syncthreads();                 // vst reads done; reuse as partial sums
    float* pts = sm;                 // [4][512]
    #pragma unroll
    for (int j = 0; j < 8; j++) pts[g * 512 + j * 64 + c] = acc[j];
    __syncthreads();

    // ---- reduce partials + bo, store ----
    #pragma unroll
    for (int i = tid; i < 512; i += 256) {
        int v = i >> 6, cc = i & 63;
        float o = (pts[i] + pts[512 + i]) + (pts[1024 + i] + pts[1536 + i])
                + bo[cc];
        int gv = ((X + (v >> 2)) * 20 + Y + ((v >> 1) & 1)) * 20 + Z + (v & 1);
        out[gv * 64 + cc] = o;
    }
}

// ---------------------------------------------------------------------------
// Launch
// d_in: 0=spatial_embeddings 1=relpos_w 2=Wq 3=bq 4=Wk 5=bk 6=Wv 7=bv 8=Wo 9=bo
// ---------------------------------------------------------------------------
extern "C" void kernel_launch(void* const* d_in, const int* in_sizes, int n_in,
                              void* d_out, int out_size)
{
    const float* se = (const float*)d_in[0];
    const float* rw = (const float*)d_in[1];
    const float* Wq = (const float*)d_in[2];
    const float* bq = (const float*)d_in[3];
    const float* Wk = (const float*)d_in[4];
    const float* bk = (const float*)d_in[5];
    const float* Wv = (const float*)d_in[6];
    const float* bv = (const float*)d_in[7];
    const float* Wo = (const float*)d_in[8];
    const float* bo = (const float*)d_in[9];
    float* out = (float*)d_out;

    cudaFuncSetAttribute(attn_kernel, cudaFuncAttributeMaxDynamicSharedMemorySize,
                         SMF * 4);

    rel_w2_kernel<<<NP + 64, 64>>>(rw, Wk, bk, Wv, bv, Wo);
    prep_kernel<<<dim3(250, 3), 256>>>(se, Wq, bq, Wk);
    qr_kernel<<<2125, 512>>>(Wo);
    attn_kernel<<<1000, 256, SMF * 4>>>(bo, out);
}

// round 7
// speedup vs baseline: 2.0791x; 1.0765x over previous
#include <cuda_runtime.h>

// ---------------------------------------------------------------------------
// CubeAttention v4. N=20, D=64, CAP=32, SCOPE=2, WIDTH=5, P=125.
//   Q  = SE@Wq+bq ; K = SE@Wk[96:]      (zero-padded 22^3 cube)
//   W2 = Wv[96:]@Wo ; V' = SE@W2        (value rows pre-multiplied by Wo)
//   krel[p] = relpos@Wk[:96]+bk ; vrel'[p] = (relpos@Wv[:96]+bv)@Wo
//   QR[v][p] = Q[v].krel[p]
//   logits[v][p] = QR + Q[v].K[gather]  (zero pad rows => QR only)
//   out[v] = sum_p sc[p]*(V'[gather] + vrel'[p]) + bo
// mask quirk: validity at (x+a,y+b,z+c) strict [1,19]; gather at (x+b,y+a,z+c)
// Block = 2x2x2 voxels, 256 thr. Region K/V' staged as float4-major
// vst4[16][217] (conflict-free for all phases). Row LUTs kill index math.
// ---------------------------------------------------------------------------

#define NV 8000
#define NP 125
#define PD 22
#define PR (PD * PD * PD)
#define S4 217                      // float4 row stride
// smem floats:
#define SM_VST 0                    // float4[16][217] = 13888 floats
#define SM_SC  13888                // [8][128]  = 1024
#define SM_QT  14912                // [64][8]   = 512
#define SM_WT  15424                // [341][8]  = 2728 (+pad)
#define SM_LG  18160                // int lutg[216]
#define SM_LP  18376                // int lutp[216]
#define SMF    18592                // 74368 B -> 3 CTAs/SM

__device__ float g_Q[NV * 64];
__device__ float g_K[PR * 64];      // zero-padded
__device__ float g_V[PR * 64];      // V' (pre-Wo), zero-padded
__device__ float g_W2[64 * 64];
__device__ float g_krelT[64 * NP];
__device__ float g_vrel[NP * 64];
__device__ float g_vrel2[NP * 64];  // vrel @ Wo
__device__ float g_QR[NV * 128];

// ---------------------------------------------------------------------------
// K1: rel tables (blocks 0..124) + W2 = Wv[96:]@Wo (blocks 125..188)
// ---------------------------------------------------------------------------
__global__ void __launch_bounds__(64) rel_w2_kernel(
    const float* __restrict__ rw,
    const float* __restrict__ Wk, const float* __restrict__ bk,
    const float* __restrict__ Wv, const float* __restrict__ bv,
    const float* __restrict__ Wo)
{
    int blk = blockIdx.x;
    int ch  = threadIdx.x;
    if (blk >= NP) {
        int i = blk - NP;
        float acc = 0.0f;
        #pragma unroll 8
        for (int k = 0; k < 64; k++)
            acc = fmaf(Wv[(96 + i) * 64 + k], Wo[k * 64 + ch], acc);
        g_W2[i * 64 + ch] = acc;
        return;
    }
    int p = blk;
    int a = p / 25, b = (p / 5) % 5, c = p % 5;
    float kk = bk[ch];
    float vv = bv[ch];
    #pragma unroll 8
    for (int j = 0; j < 32; j++) {
        float ra = rw[a * 32 + j];
        float rb = rw[b * 32 + j];
        float rc = rw[c * 32 + j];
        kk = fmaf(ra, Wk[j * 64 + ch], kk);
        kk = fmaf(rb, Wk[(32 + j) * 64 + ch], kk);
        kk = fmaf(rc, Wk[(64 + j) * 64 + ch], kk);
        vv = fmaf(ra, Wv[j * 64 + ch], vv);
        vv = fmaf(rb, Wv[(32 + j) * 64 + ch], vv);
        vv = fmaf(rc, Wv[(64 + j) * 64 + ch], vv);
    }
    g_krelT[ch * NP + p] = kk;
    g_vrel[p * 64 + ch]  = vv;
}

// ---------------------------------------------------------------------------
// K2: prep. sel 0: Q = SE@Wq+bq ; 1: K = SE@Wk[96:] ; 2: V' = SE@W2.
// ---------------------------------------------------------------------------
__global__ void __launch_bounds__(256) prep_kernel(
    const float* __restrict__ se,
    const float* __restrict__ Wq, const float* __restrict__ bq,
    const float* __restrict__ Wk)
{
    __shared__ float Wsm[64 * 64];
    __shared__ float ssm[32 * 64];
    int sel = blockIdx.y;
    int tid = threadIdx.x;
    const float* W = (sel == 0) ? Wq : (sel == 1) ? (Wk + 96 * 64) : g_W2;

    #pragma unroll
    for (int i = tid; i < 1024; i += 256)
        ((float4*)Wsm)[i] = ((const float4*)W)[i];
    int base = blockIdx.x * 32;
    #pragma unroll
    for (int i = tid; i < 512; i += 256)
        ((float4*)ssm)[i] = ((const float4*)(se + base * 64))[i];
    __syncthreads();

    int c  = tid & 63;
    int r0 = (tid >> 6) * 8;
    float acc[8];
    float bias = (sel == 0) ? bq[c] : 0.0f;
    #pragma unroll
    for (int j = 0; j < 8; j++) acc[j] = bias;

    #pragma unroll 4
    for (int k = 0; k < 64; k++) {
        float wv = Wsm[k * 64 + c];
        #pragma unroll
        for (int j = 0; j < 8; j++)
            acc[j] = fmaf(ssm[(r0 + j) * 64 + k], wv, acc[j]);
    }
    #pragma unroll
    for (int j = 0; j < 8; j++) {
        int v = base + r0 + j;
        if (sel == 0) {
            g_Q[v * 64 + c] = acc[j];
        } else {
            int x = v / 400, y = (v / 20) % 20, z = v % 20;
            int pi = ((x + 2) * PD + (y + 2)) * PD + (z + 2);
            ((sel == 1) ? g_K : g_V)[pi * 64 + c] = acc[j];
        }
    }
}

// ---------------------------------------------------------------------------
// K3: QR (blocks 0..1999) + vrel2 = vrel@Wo (blocks 2000..2124)
// ---------------------------------------------------------------------------
__global__ void __launch_bounds__(512) qr_kernel(const float* __restrict__ Wo)
{
    __shared__ float qsm[4 * 64];
    int tid = threadIdx.x;
    if (blockIdx.x >= 2000) {
        int p = blockIdx.x - 2000;
        if (tid < 64) {
            float acc = 0.0f;
            #pragma unroll 8
            for (int k = 0; k < 64; k++)
                acc = fmaf(g_vrel[p * 64 + k], Wo[k * 64 + tid], acc);
            g_vrel2[p * 64 + tid] = acc;
        }
        return;
    }
    int h = tid >> 7;
    int p = tid & 127;
    int v = blockIdx.x * 4 + h;
    if (p < 64) qsm[h * 64 + p] = g_Q[v * 64 + p];
    __syncthreads();
    if (p < NP) {
        float acc = 0.0f;
        #pragma unroll 8
        for (int k = 0; k < 64; k++)
            acc = fmaf(qsm[h * 64 + k], g_krelT[k * NP + p], acc);
        g_QR[v * 128 + p] = acc;
    }
}

// ---------------------------------------------------------------------------
// K4: attention. 2x2x2 voxels / block, 256 threads.
// ---------------------------------------------------------------------------
__global__ void __launch_bounds__(256) attn_kernel(
    const float* __restrict__ bo, float* __restrict__ out)
{
    extern __shared__ float sm[];
    float4* vst4 = (float4*)(sm + SM_VST);       // [c4][S4]
    float*  sc   = sm + SM_SC;
    float*  qt   = sm + SM_QT;
    float*  wt   = sm + SM_WT;
    int*    lutg = (int*)(sm + SM_LG);
    int*    lutp = (int*)(sm + SM_LP);

    int tid = threadIdx.x;
    int bz = blockIdx.x % 10, by = (blockIdx.x / 10) % 10, bx = blockIdx.x / 100;
    int X = bx * 2, Y = by * 2, Z = bz * 2;
    int prow = (X * PD + Y) * PD + Z;

    // ---- stage K region (builds LUTs), q, QR ----
    const float4* K4 = (const float4*)g_K;
    #pragma unroll
    for (int i = tid; i < 216 * 16; i += 256) {
        int r = i >> 4, c4 = i & 15;
        int rx = r / 36, rem = r - rx * 36, ry = rem / 6, rz = rem - ry * 6;
        int gb = (prow + (rx * PD + ry) * PD + rz) * 16;
        if (c4 == 0) {
            lutg[r] = gb;
            lutp[r] = rx | (ry << 8) | (rz << 16);
        }
        vst4[c4 * S4 + r] = K4[gb + c4];
    }
    #pragma unroll
    for (int i = tid; i < 512; i += 256) {
        int v = i >> 6, k = i & 63;
        int gv = ((X + (v >> 2)) * 20 + Y + ((v >> 1) & 1)) * 20 + Z + (v & 1);
        qt[k * 8 + v] = g_Q[gv * 64 + k];
    }
    #pragma unroll
    for (int i = tid; i < 1024; i += 256) {
        int v = i >> 7, p = i & 127;
        int gv = ((X + (v >> 2)) * 20 + Y + ((v >> 1) & 1)) * 20 + Z + (v & 1);
        sc[i] = (p < NP) ? g_QR[gv * 128 + p] : -1e30f;
    }
    __syncthreads();

    // ---- phase 1: rowdot [8 x 216] + masked scatter into logits ----
    if (tid < 216) {
        int r = tid;
        float acc[8];
        #pragma unroll
        for (int j = 0; j < 8; j++) acc[j] = 0.0f;
        #pragma unroll 4
        for (int k4 = 0; k4 < 16; k4++) {
            float4 kv = vst4[k4 * S4 + r];
            const float* qb = qt + k4 * 32;
            #pragma unroll
            for (int kk = 0; kk < 4; kk++) {
                float k1 = (kk == 0) ? kv.x : (kk == 1) ? kv.y : (kk == 2) ? kv.z : kv.w;
                float4 qa0 = *(const float4*)(qb + kk * 8);
                float4 qa1 = *(const float4*)(qb + kk * 8 + 4);
                acc[0] = fmaf(k1, qa0.x, acc[0]); acc[1] = fmaf(k1, qa0.y, acc[1]);
                acc[2] = fmaf(k1, qa0.z, acc[2]); acc[3] = fmaf(k1, qa0.w, acc[3]);
                acc[4] = fmaf(k1, qa1.x, acc[4]); acc[5] = fmaf(k1, qa1.y, acc[5]);
                acc[6] = fmaf(k1, qa1.z, acc[6]); acc[7] = fmaf(k1, qa1.w, acc[7]);
            }
        }
        int pk = lutp[r];
        int rx = pk & 255, ry = (pk >> 8) & 255, rz = pk >> 16;
        #pragma unroll
        for (int v = 0; v < 8; v++) {
            int lx = v >> 2, ly = (v >> 1) & 1, lz = v & 1;
            int a = ry - ly, b = rx - lx, c = rz - lz;
            if (((unsigned)a < 5u) & ((unsigned)b < 5u) & ((unsigned)c < 5u)) {
                int p = (a * 5 + b) * 5 + c;
                int mx = X + lx + a - 2, my = Y + ly + b - 2, mz = Z + lz + c - 2;
                bool mv = (mx >= 1) & (mx <= 19) & (my >= 1) & (my <= 19)
                        & (mz >= 1) & (mz <= 19);
                sc[v * 128 + p] = mv ? (sc[v * 128 + p] + acc[v]) : -1e9f;
            }
        }
    }
    __syncthreads();

    // ---- phase 2: per-voxel softmax (warp = voxel); masked -> exact 0 ----
    {
        int w = tid >> 5, lane = tid & 31;
        float l0 = sc[w * 128 + lane];
        float l1 = sc[w * 128 + lane + 32];
        float l2 = sc[w * 128 + lane + 64];
        float l3 = (lane < 29) ? sc[w * 128 + lane + 96] : -1e30f;
        float m = fmaxf(fmaxf(l0, l1), fmaxf(l2, l3));
        #pragma unroll
        for (int o = 16; o; o >>= 1)
            m = fmaxf(m, __shfl_xor_sync(0xffffffffu, m, o));
        float e0 = __expf(l0 - m), e1 = __expf(l1 - m);
        float e2 = __expf(l2 - m), e3 = __expf(l3 - m);
        float s = (e0 + e1) + (e2 + e3);
        #pragma unroll
        for (int o = 16; o; o >>= 1)
            s += __shfl_xor_sync(0xffffffffu, s, o);
        float inv = 1.0f / s;
        sc[w * 128 + lane]      = e0 * inv;
        sc[w * 128 + lane + 32] = e1 * inv;
        sc[w * 128 + lane + 64] = e2 * inv;
        if (lane < 29) sc[w * 128 + lane + 96] = e3 * inv;
    }

    // ---- stage V' region over K buffer (uses LUT; independent of softmax) --
    {
        const float4* V4 = (const float4*)g_V;
        #pragma unroll
        for (int i = tid; i < 216 * 16; i += 256) {
            int r = i >> 4, c4 = i & 15;
            vst4[c4 * S4 + r] = V4[lutg[r] + c4];
        }
    }
    __syncthreads();

    // ---- build weight table wt[341][8] (zeros outside window) ----
    for (int i = tid; i < 341 * 8; i += 256) {
        int r = i >> 3, v = i & 7;
        float w;
        if (r < 216) {
            int pk = lutp[r];
            int rx = pk & 255, ry = (pk >> 8) & 255, rz = pk >> 16;
            int lx = v >> 2, ly = (v >> 1) & 1, lz = v & 1;
            int a = ry - ly, b = rx - lx, c = rz - lz;
            w = (((unsigned)a < 5u) & ((unsigned)b < 5u) & ((unsigned)c < 5u))
                ? sc[v * 128 + (a * 5 + b) * 5 + c] : 0.0f;
        } else {
            w = sc[v * 128 + (r - 216)];
        }
        wt[i] = w;
    }
    __syncthreads();

    // ---- phase 3: value GEMM  out[8][64] = wt[341][8]^T @ rows[341][64] ----
    int g = tid >> 6, c = tid & 63;
    int c4i = (c >> 2) * S4;
    int cc4 = c & 3;
    float acc[8];
    #pragma unroll
    for (int j = 0; j < 8; j++) acc[j] = 0.0f;
    {
        int rA = (g * 341) >> 2;
        int rB = ((g + 1) * 341) >> 2;
        int rS = rB < 216 ? rB : 216;       // smem segment end
        #pragma unroll 4
        for (int r = rA; r < rS; r++) {
            float4 vf = vst4[c4i + r];
            float val = (cc4 == 0) ? vf.x : (cc4 == 1) ? vf.y : (cc4 == 2) ? vf.z : vf.w;
            float4 w0 = *(const float4*)(wt + r * 8);
            float4 w1 = *(const float4*)(wt + r * 8 + 4);
            acc[0] = fmaf(w0.x, val, acc[0]); acc[1] = fmaf(w0.y, val, acc[1]);
            acc[2] = fmaf(w0.z, val, acc[2]); acc[3] = fmaf(w0.w, val, acc[3]);
            acc[4] = fmaf(w1.x, val, acc[4]); acc[5] = fmaf(w1.y, val, acc[5]);
            acc[6] = fmaf(w1.z, val, acc[6]); acc[7] = fmaf(w1.w, val, acc[7]);
        }
        int rG = rA > 216 ? rA : 216;       // global segment start
        #pragma unroll 4
        for (int r = rG; r < rB; r++) {
            float val = g_vrel2[(r - 216) * 64 + c];
            float4 w0 = *(const float4*)(wt + r * 8);
            float4 w1 = *(const float4*)(wt + r * 8 + 4);
            acc[0] = fmaf(w0.x, val, acc[0]); acc[1] = fmaf(w0.y, val, acc[1]);
            acc[2] = fmaf(w0.z, val, acc[2]); acc[3] = fmaf(w0.w, val, acc[3]);
            acc[4] = fmaf(w1.x, val, acc[4]); acc[5] = fmaf(w1.y, val, acc[5]);
            acc[6] = fmaf(w1.z, val, acc[6]); acc[7] = fmaf(w1.w, val, acc[7]);
        }
    }
    __syncthreads();                 // vst reads done; reuse as partial sums
    float* pts = sm;                 // [4][512]
    #pragma unroll
    for (int j = 0; j < 8; j++) pts[g * 512 + j * 64 + c] = acc[j];
    __syncthreads();

    // ---- reduce partials + bo, store ----
    #pragma unroll
    for (int i = tid; i < 512; i += 256) {
        int v = i >> 6, cc = i & 63;
        float o = (pts[i] + pts[512 + i]) + (pts[1024 + i] + pts[1536 + i])
                + bo[cc];
        int gv = ((X + (v >> 2)) * 20 + Y + ((v >> 1) & 1)) * 20 + Z + (v & 1);
        out[gv * 64 + cc] = o;
    }
}

// ---------------------------------------------------------------------------
// Launch
// d_in: 0=spatial_embeddings 1=relpos_w 2=Wq 3=bq 4=Wk 5=bk 6=Wv 7=bv 8=Wo 9=bo
// ---------------------------------------------------------------------------
extern "C" void kernel_launch(void* const* d_in, const int* in_sizes, int n_in,
                              void* d_out, int out_size)
{
    const float* se = (const float*)d_in[0];
    const float* rw = (const float*)d_in[1];
    const float* Wq = (const float*)d_in[2];
    const float* bq = (const float*)d_in[3];
    const float* Wk = (const float*)d_in[4];
    const float* bk = (const float*)d_in[5];
    const float* Wv = (const float*)d_in[6];
    const float* bv = (const float*)d_in[7];
    const float* Wo = (const float*)d_in[8];
    const float* bo = (const float*)d_in[9];
    float* out = (float*)d_out;

    cudaFuncSetAttribute(attn_kernel, cudaFuncAttributeMaxDynamicSharedMemorySize,
                         SMF * 4);

    rel_w2_kernel<<<NP + 64, 64>>>(rw, Wk, bk, Wv, bv, Wo);
    prep_kernel<<<dim3(250, 3), 256>>>(se, Wq, bq, Wk);
    qr_kernel<<<2125, 512>>>(Wo);
    attn_kernel<<<1000, 256, SMF * 4>>>(bo, out);
}